// round 16
// baseline (speedup 1.0000x reference)
#include <cuda_runtime.h>
#include <cuda_bf16.h>
#include <cstdint>

// RotationComponent: w_rotated = w @ rot, a_rotated = x @ rot, rot a
// normalized randomized Hadamard: rot[i,j] = H[i,j] * rot[0,j], H Sylvester,
// rot[0,j] = s_j * 2^-6 exactly (s_j = +-1, 2^-6 exact in fp32). Hence
//   (v @ rot)[j] = FWHT(v)[j] * s_j * 2^-6.
//
// SINGLE launch, TWO rows per CTA (grid 6144; rows bid and bid+6144), each in
// its own 16KB smem buffer, both TMA bulk loads issued back-to-back in the
// prologue -> row B's load latency fully hidden behind row A's compute.
// __launch_bounds__(256, 6): cap regs at 42 -> 6 CTAs/SM (smem 33KB x 6 =
// 198KB < 228KB carveout) -> 12 rows in flight per SM (+50% vs natural regs).
// Sign mask (depends only on threadIdx) packed from 4 rot float4 loads in the
// prologue, overlapped with the TMA wait; epilogue = XOR + exact 2^-6 mul.
//
// FWHT phases (shuffle-free, conflict-free swizzled smem):
//   P1: regs = i-bits {9..6}   i = (t>>6)*1024 + r*64 + (t&63)
//   P2: regs = i-bits {5..2}   i = J*64 + r*4 + e2
//   P3: regs = i-bits {11,10,1,0} -> 4 aligned float4, STG.128
// Swizzle: phys = i ^ ((i>>4) & 28) (16B-granular, preserves LDS.128 blocks).

#define DIM 4096
#define W_ROWS 4096
#define THREADS 256
#define GRID 6144
#define ROW_BYTES (DIM * 4)
#define INV64 0.015625f

__device__ __forceinline__ int swz(int i)
{
    return i ^ ((i >> 4) & 28);
}

__device__ __forceinline__ uint32_t smem_u32(const void* p)
{
    uint32_t a;
    asm("{ .reg .u64 t; cvta.to.shared.u64 t, %1; cvt.u32.u64 %0, t; }"
        : "=r"(a) : "l"(p));
    return a;
}

__device__ __forceinline__ void mbar_wait0(uint32_t mb)
{
    asm volatile(
        "{\n\t"
        ".reg .pred P1;\n\t"
        "WAIT_LOOP_%=:\n\t"
        "mbarrier.try_wait.parity.acquire.cta.shared::cta.b64 P1, [%0], 0, 0x989680;\n\t"
        "@P1 bra.uni WAIT_DONE_%=;\n\t"
        "bra.uni WAIT_LOOP_%=;\n\t"
        "WAIT_DONE_%=:\n\t"
        "}"
        :: "r"(mb) : "memory");
}

// One full 4096-pt FWHT + sign-scale + store for one row held in buf.
__device__ __forceinline__ void process_row(float* buf, float* dst,
                                            unsigned mask,
                                            int p1_base, int p2_base,
                                            int p3_base)
{
    float v[16];

    // P1: linear read; butterflies on i-bits {9..6}
    #pragma unroll
    for (int r = 0; r < 16; r++) v[r] = buf[p1_base + r * 64];
    #pragma unroll
    for (int m = 8; m >= 1; m >>= 1) {
        #pragma unroll
        for (int r = 0; r < 16; r++) {
            if ((r & m) == 0) {
                float a = v[r], b = v[r | m];
                v[r]     = a + b;
                v[r | m] = a - b;
            }
        }
    }
    __syncthreads();   // in-place reuse: all P1 reads done

    // T1: swizzled write (conflict-free)
    #pragma unroll
    for (int r = 0; r < 16; r++) buf[swz(p1_base + r * 64)] = v[r];
    __syncthreads();

    // P2: butterflies on i-bits {5..2}
    #pragma unroll
    for (int r = 0; r < 16; r++) v[r] = buf[swz(p2_base + r * 4)];
    #pragma unroll
    for (int m = 8; m >= 1; m >>= 1) {
        #pragma unroll
        for (int r = 0; r < 16; r++) {
            if ((r & m) == 0) {
                float a = v[r], b = v[r | m];
                v[r]     = a + b;
                v[r | m] = a - b;
            }
        }
    }
    #pragma unroll
    for (int r = 0; r < 16; r++) buf[swz(p2_base + r * 4)] = v[r];
    __syncthreads();

    // P3: LDS.128; butterflies on i-bits {11,10,1,0}
    #pragma unroll
    for (int c = 0; c < 4; c++) {
        float4 q = *(const float4*)(buf + swz(c * 1024 + p3_base));
        v[c * 4 + 0] = q.x;
        v[c * 4 + 1] = q.y;
        v[c * 4 + 2] = q.z;
        v[c * 4 + 3] = q.w;
    }
    #pragma unroll
    for (int m = 8; m >= 1; m >>= 1) {
        #pragma unroll
        for (int r = 0; r < 16; r++) {
            if ((r & m) == 0) {
                float a = v[r], b = v[r | m];
                v[r]     = a + b;
                v[r | m] = a - b;
            }
        }
    }

    // Epilogue: sign-XOR + exact 2^-6 scale, 4x STG.128
    #pragma unroll
    for (int c = 0; c < 4; c++) {
        float4 o;
        #pragma unroll
        for (int e = 0; e < 4; e++) {
            const int k = c * 4 + e;
            const unsigned sb = (mask >> k) << 31;
            ((float*)&o)[e] =
                __int_as_float(__float_as_int(v[k]) ^ (int)sb) * INV64;
        }
        *(float4*)(dst + c * 1024 + p3_base) = o;
    }
}

__global__ __launch_bounds__(THREADS, 6)
void fwht_rotate_kernel(const float* __restrict__ w,
                        const float* __restrict__ x,
                        const float* __restrict__ rot,
                        float* __restrict__ out)
{
    __shared__ float bufA[DIM];
    __shared__ float bufB[DIM];
    __shared__ __align__(8) unsigned long long mbar[2];

    const int t    = threadIdx.x;
    const int lane = t & 31;
    const int warp = t >> 5;

    const int rowA = blockIdx.x;          // 0..6143
    const int rowB = rowA + GRID;         // 6144..12287

    const uint32_t mb0 = smem_u32(&mbar[0]);
    const uint32_t mb1 = smem_u32(&mbar[1]);

    // ---- Prologue: init both mbars, issue BOTH TMA bulk loads ----
    if (t == 0) {
        const float* srcA = (rowA < W_ROWS)
            ? (w + (size_t)rowA * DIM)
            : (x + (size_t)(rowA - W_ROWS) * DIM);
        const float* srcB = (rowB < W_ROWS)
            ? (w + (size_t)rowB * DIM)
            : (x + (size_t)(rowB - W_ROWS) * DIM);
        asm volatile("mbarrier.init.shared.b64 [%0], 1;" :: "r"(mb0) : "memory");
        asm volatile("mbarrier.init.shared.b64 [%0], 1;" :: "r"(mb1) : "memory");
        asm volatile("fence.proxy.async.shared::cta;" ::: "memory");
        asm volatile("mbarrier.arrive.expect_tx.shared.b64 _, [%0], %1;"
                     :: "r"(mb0), "r"((uint32_t)ROW_BYTES) : "memory");
        asm volatile("cp.async.bulk.shared::cta.global.mbarrier::complete_tx::bytes "
                     "[%0], [%1], %2, [%3];"
                     :: "r"(smem_u32(bufA)), "l"(srcA),
                        "r"((uint32_t)ROW_BYTES), "r"(mb0) : "memory");
        asm volatile("mbarrier.arrive.expect_tx.shared.b64 _, [%0], %1;"
                     :: "r"(mb1), "r"((uint32_t)ROW_BYTES) : "memory");
        asm volatile("cp.async.bulk.shared::cta.global.mbarrier::complete_tx::bytes "
                     "[%0], [%1], %2, [%3];"
                     :: "r"(smem_u32(bufB)), "l"(srcB),
                        "r"((uint32_t)ROW_BYTES), "r"(mb1) : "memory");
    }

    // ---- Pack per-thread sign mask from rot row 0 (overlaps TMA wait);
    //      amortized over BOTH rows ----
    const int p3_base = t * 4;
    unsigned mask = 0;
    #pragma unroll
    for (int c = 0; c < 4; c++) {
        float4 s = __ldg((const float4*)(rot + c * 1024 + p3_base));
        mask |= (__float_as_uint(s.x) >> 31) << (c * 4 + 0);
        mask |= (__float_as_uint(s.y) >> 31) << (c * 4 + 1);
        mask |= (__float_as_uint(s.z) >> 31) << (c * 4 + 2);
        mask |= (__float_as_uint(s.w) >> 31) << (c * 4 + 3);
    }

    const int p1_base = (t >> 6) * 1024 + (t & 63);
    const int p2_base = (warp * 8 + ((lane >> 2) & 7)) * 64 + (lane & 3);

    // ---- Barrier-init visibility, then row A (its TMA was issued first) ----
    __syncthreads();
    mbar_wait0(mb0);
    process_row(bufA, out + (size_t)rowA * DIM, mask,
                p1_base, p2_base, p3_base);

    // ---- Row B: load fully hidden behind row A's compute ----
    mbar_wait0(mb1);
    __syncthreads();   // keep warps phase-aligned entering row B
    process_row(bufB, out + (size_t)rowB * DIM, mask,
                p1_base, p2_base, p3_base);
}

extern "C" void kernel_launch(void* const* d_in, const int* in_sizes, int n_in,
                              void* d_out, int out_size)
{
    const float* w   = (const float*)d_in[0];   // [4096, 4096]
    const float* x   = (const float*)d_in[1];   // [4, 2048, 4096]
    const float* rot = (const float*)d_in[2];   // [4096, 4096]
    float* out = (float*)d_out;                 // w_rotated then a_rotated

    (void)in_sizes; (void)n_in; (void)out_size;

    fwht_rotate_kernel<<<GRID, THREADS>>>(w, x, rot, out);
}

// round 17
// speedup vs baseline: 1.1154x; 1.1154x over previous
#include <cuda_runtime.h>
#include <cuda_bf16.h>
#include <cstdint>

// RotationComponent: w_rotated = w @ rot, a_rotated = x @ rot, rot a
// normalized randomized Hadamard: rot[i,j] = H[i,j] * rot[0,j], H Sylvester,
// rot[0,j] = s_j * 2^-6 exactly (s_j = +-1, 2^-6 exact in fp32). Hence
//   (v @ rot)[j] = FWHT(v)[j] * s_j * 2^-6.
//
// SINGLE launch, TWO rows per CTA (grid 6144; rows bid and bid+6144), each in
// its own 16KB smem buffer, both TMA bulk loads issued back-to-back in the
// prologue -> row B's load latency fully hidden behind row A's compute.
// __launch_bounds__(256, 5): 51 regs -> 5 CTAs/SM = 10 rows in flight
// (R16 showed 42 regs spills; 51 leaves ~19 regs over the 32-reg single-row
// floor, so no spill expected). Live state across rows minimized: dst
// recomputed per row, no held pointers.
// Sign mask (depends only on threadIdx) packed from 4 rot float4 loads in the
// prologue, overlapped with the TMA wait; epilogue = XOR + exact 2^-6 mul.
//
// FWHT phases (shuffle-free, conflict-free swizzled smem):
//   P1: regs = i-bits {9..6}   i = (t>>6)*1024 + r*64 + (t&63)
//   P2: regs = i-bits {5..2}   i = J*64 + r*4 + e2
//   P3: regs = i-bits {11,10,1,0} -> 4 aligned float4, STG.128
// Swizzle: phys = i ^ ((i>>4) & 28) (16B-granular, preserves LDS.128 blocks).

#define DIM 4096
#define W_ROWS 4096
#define THREADS 256
#define GRID 6144
#define ROW_BYTES (DIM * 4)
#define INV64 0.015625f

__device__ __forceinline__ int swz(int i)
{
    return i ^ ((i >> 4) & 28);
}

__device__ __forceinline__ uint32_t smem_u32(const void* p)
{
    uint32_t a;
    asm("{ .reg .u64 t; cvta.to.shared.u64 t, %1; cvt.u32.u64 %0, t; }"
        : "=r"(a) : "l"(p));
    return a;
}

__device__ __forceinline__ void mbar_wait0(uint32_t mb)
{
    asm volatile(
        "{\n\t"
        ".reg .pred P1;\n\t"
        "WAIT_LOOP_%=:\n\t"
        "mbarrier.try_wait.parity.acquire.cta.shared::cta.b64 P1, [%0], 0, 0x989680;\n\t"
        "@P1 bra.uni WAIT_DONE_%=;\n\t"
        "bra.uni WAIT_LOOP_%=;\n\t"
        "WAIT_DONE_%=:\n\t"
        "}"
        :: "r"(mb) : "memory");
}

// One full 4096-pt FWHT + sign-scale + store for one row held in buf.
__device__ __forceinline__ void process_row(float* buf, float* dst,
                                            unsigned mask,
                                            int p1_base, int p2_base,
                                            int p3_base)
{
    float v[16];

    // P1: linear read; butterflies on i-bits {9..6}
    #pragma unroll
    for (int r = 0; r < 16; r++) v[r] = buf[p1_base + r * 64];
    #pragma unroll
    for (int m = 8; m >= 1; m >>= 1) {
        #pragma unroll
        for (int r = 0; r < 16; r++) {
            if ((r & m) == 0) {
                float a = v[r], b = v[r | m];
                v[r]     = a + b;
                v[r | m] = a - b;
            }
        }
    }
    __syncthreads();   // in-place reuse: all P1 reads done

    // T1: swizzled write (conflict-free)
    #pragma unroll
    for (int r = 0; r < 16; r++) buf[swz(p1_base + r * 64)] = v[r];
    __syncthreads();

    // P2: butterflies on i-bits {5..2}
    #pragma unroll
    for (int r = 0; r < 16; r++) v[r] = buf[swz(p2_base + r * 4)];
    #pragma unroll
    for (int m = 8; m >= 1; m >>= 1) {
        #pragma unroll
        for (int r = 0; r < 16; r++) {
            if ((r & m) == 0) {
                float a = v[r], b = v[r | m];
                v[r]     = a + b;
                v[r | m] = a - b;
            }
        }
    }
    #pragma unroll
    for (int r = 0; r < 16; r++) buf[swz(p2_base + r * 4)] = v[r];
    __syncthreads();

    // P3: LDS.128; butterflies on i-bits {11,10,1,0}
    #pragma unroll
    for (int c = 0; c < 4; c++) {
        float4 q = *(const float4*)(buf + swz(c * 1024 + p3_base));
        v[c * 4 + 0] = q.x;
        v[c * 4 + 1] = q.y;
        v[c * 4 + 2] = q.z;
        v[c * 4 + 3] = q.w;
    }
    #pragma unroll
    for (int m = 8; m >= 1; m >>= 1) {
        #pragma unroll
        for (int r = 0; r < 16; r++) {
            if ((r & m) == 0) {
                float a = v[r], b = v[r | m];
                v[r]     = a + b;
                v[r | m] = a - b;
            }
        }
    }

    // Epilogue: sign-XOR + exact 2^-6 scale, 4x STG.128
    #pragma unroll
    for (int c = 0; c < 4; c++) {
        float4 o;
        #pragma unroll
        for (int e = 0; e < 4; e++) {
            const int k = c * 4 + e;
            const unsigned sb = (mask >> k) << 31;
            ((float*)&o)[e] =
                __int_as_float(__float_as_int(v[k]) ^ (int)sb) * INV64;
        }
        *(float4*)(dst + c * 1024 + p3_base) = o;
    }
}

__global__ __launch_bounds__(THREADS, 5)
void fwht_rotate_kernel(const float* __restrict__ w,
                        const float* __restrict__ x,
                        const float* __restrict__ rot,
                        float* __restrict__ out)
{
    __shared__ float bufA[DIM];
    __shared__ float bufB[DIM];
    __shared__ __align__(8) unsigned long long mbar[2];

    const int t    = threadIdx.x;
    const int lane = t & 31;
    const int warp = t >> 5;

    const uint32_t mb0 = smem_u32(&mbar[0]);
    const uint32_t mb1 = smem_u32(&mbar[1]);

    // ---- Prologue: init both mbars, issue BOTH TMA bulk loads ----
    if (t == 0) {
        const int rowA = blockIdx.x;
        const int rowB = rowA + GRID;
        const float* srcA = (rowA < W_ROWS)
            ? (w + (size_t)rowA * DIM)
            : (x + (size_t)(rowA - W_ROWS) * DIM);
        const float* srcB = (rowB < W_ROWS)
            ? (w + (size_t)rowB * DIM)
            : (x + (size_t)(rowB - W_ROWS) * DIM);
        asm volatile("mbarrier.init.shared.b64 [%0], 1;" :: "r"(mb0) : "memory");
        asm volatile("mbarrier.init.shared.b64 [%0], 1;" :: "r"(mb1) : "memory");
        asm volatile("fence.proxy.async.shared::cta;" ::: "memory");
        asm volatile("mbarrier.arrive.expect_tx.shared.b64 _, [%0], %1;"
                     :: "r"(mb0), "r"((uint32_t)ROW_BYTES) : "memory");
        asm volatile("cp.async.bulk.shared::cta.global.mbarrier::complete_tx::bytes "
                     "[%0], [%1], %2, [%3];"
                     :: "r"(smem_u32(bufA)), "l"(srcA),
                        "r"((uint32_t)ROW_BYTES), "r"(mb0) : "memory");
        asm volatile("mbarrier.arrive.expect_tx.shared.b64 _, [%0], %1;"
                     :: "r"(mb1), "r"((uint32_t)ROW_BYTES) : "memory");
        asm volatile("cp.async.bulk.shared::cta.global.mbarrier::complete_tx::bytes "
                     "[%0], [%1], %2, [%3];"
                     :: "r"(smem_u32(bufB)), "l"(srcB),
                        "r"((uint32_t)ROW_BYTES), "r"(mb1) : "memory");
    }

    // ---- Pack per-thread sign mask from rot row 0 (overlaps TMA wait);
    //      amortized over BOTH rows ----
    const int p3_base = t * 4;
    unsigned mask = 0;
    #pragma unroll
    for (int c = 0; c < 4; c++) {
        float4 s = __ldg((const float4*)(rot + c * 1024 + p3_base));
        mask |= (__float_as_uint(s.x) >> 31) << (c * 4 + 0);
        mask |= (__float_as_uint(s.y) >> 31) << (c * 4 + 1);
        mask |= (__float_as_uint(s.z) >> 31) << (c * 4 + 2);
        mask |= (__float_as_uint(s.w) >> 31) << (c * 4 + 3);
    }

    const int p1_base = (t >> 6) * 1024 + (t & 63);
    const int p2_base = (warp * 8 + ((lane >> 2) & 7)) * 64 + (lane & 3);

    // ---- Barrier-init visibility, then row A (its TMA was issued first) ----
    __syncthreads();
    mbar_wait0(mb0);
    process_row(bufA, out + (size_t)blockIdx.x * DIM, mask,
                p1_base, p2_base, p3_base);

    // ---- Row B: load fully hidden behind row A's compute; per-thread mbar
    //      wait is sufficient (bufA/bufB disjoint, no cross-buffer hazard) ----
    mbar_wait0(mb1);
    process_row(bufB, out + (size_t)(blockIdx.x + GRID) * DIM, mask,
                p1_base, p2_base, p3_base);
}

extern "C" void kernel_launch(void* const* d_in, const int* in_sizes, int n_in,
                              void* d_out, int out_size)
{
    const float* w   = (const float*)d_in[0];   // [4096, 4096]
    const float* x   = (const float*)d_in[1];   // [4, 2048, 4096]
    const float* rot = (const float*)d_in[2];   // [4096, 4096]
    float* out = (float*)d_out;                 // w_rotated then a_rotated

    (void)in_sizes; (void)n_in; (void)out_size;

    fwht_rotate_kernel<<<GRID, THREADS>>>(w, x, rot, out);
}